// round 6
// baseline (speedup 1.0000x reference)
#include <cuda_runtime.h>
#include <cuda_bf16.h>

#define N_NODES_C 200000
#define N_GRAPHS_C 1024

// ---------------- static device scratch (no allocs allowed) ----------------
// 16B alignment: accessed via float4 / red.v4.f32.
__device__ __align__(16) float g_bufA[(size_t)N_NODES_C * 64];
__device__ __align__(16) float g_bufB[(size_t)N_NODES_C * 64];
__device__ __align__(16) float g_bufC[(size_t)N_NODES_C * 32];
__device__ __align__(16) int   g_deg[N_NODES_C];
__device__ __align__(16) float g_dinv[N_NODES_C];
__device__ __align__(16) float g_gmax[N_GRAPHS_C * 32];
__device__ __align__(16) float g_gsum[N_GRAPHS_C * 32];
__device__ __align__(16) float g_gcnt[N_GRAPHS_C];

// ---------------- helpers ----------------
__device__ __forceinline__ void red_add_v4(float* addr, float4 v) {
    asm volatile("red.global.add.v4.f32 [%0], {%1, %2, %3, %4};"
                 :: "l"(addr), "f"(v.x), "f"(v.y), "f"(v.z), "f"(v.w)
                 : "memory");
}

__device__ __forceinline__ unsigned long long fma2(unsigned long long a,
                                                   unsigned long long b,
                                                   unsigned long long c) {
    unsigned long long d;
    asm("fma.rn.f32x2 %0, %1, %2, %3;" : "=l"(d) : "l"(a), "l"(b), "l"(c));
    return d;
}

__device__ __forceinline__ unsigned long long pack2(float x) {
    unsigned long long r;
    asm("mov.b64 %0, {%1, %1};" : "=l"(r) : "r"(__float_as_uint(x)));
    return r;
}

// ---------------- degree / norm ----------------
__global__ void deg_kernel(const int* __restrict__ dst, int* __restrict__ deg, int E) {
    int e = blockIdx.x * blockDim.x + threadIdx.x;
    if (e < E) atomicAdd(&deg[dst[e]], 1);
}

__global__ void dinv_kernel(const int* __restrict__ deg, float* __restrict__ dinv, int N) {
    int i = blockIdx.x * blockDim.x + threadIdx.x;
    if (i < N) dinv[i] = rsqrtf((float)(deg[i] + 1));  // +1 self-loop
}

// ---------------- prep: optional ReLU on input, write activated copy, init agg ----------------
// agg[i][c] = dinv[i]^2 * act(in[i][c]) + (HASB ? b[c] : 0)
template<int C, bool RELU_IN, bool HASB, bool WRITEACT>
__global__ void prep_kernel(const float* __restrict__ in, float* __restrict__ actout,
                            float* __restrict__ agg, const float* __restrict__ dinv,
                            const float* __restrict__ b, int N) {
    const int TPN = C / 4;
    int gid = blockIdx.x * blockDim.x + threadIdx.x;
    int node = gid / TPN;
    int j = gid % TPN;
    if (node >= N) return;
    size_t off = (size_t)node * C + j * 4;
    float4 v = *(const float4*)(in + off);
    if (RELU_IN) {
        v.x = fmaxf(v.x, 0.f); v.y = fmaxf(v.y, 0.f);
        v.z = fmaxf(v.z, 0.f); v.w = fmaxf(v.w, 0.f);
    }
    if (WRITEACT) *(float4*)(actout + off) = v;
    float di = dinv[node];
    float s = di * di;
    float4 a;
    if (HASB) {
        float4 bb;
        bb.x = b[j * 4 + 0]; bb.y = b[j * 4 + 1];
        bb.z = b[j * 4 + 2]; bb.w = b[j * 4 + 3];
        a.x = fmaf(s, v.x, bb.x); a.y = fmaf(s, v.y, bb.y);
        a.z = fmaf(s, v.z, bb.z); a.w = fmaf(s, v.w, bb.w);
    } else {
        a.x = s * v.x; a.y = s * v.y; a.z = s * v.z; a.w = s * v.w;
    }
    *(float4*)(agg + off) = a;
}

// ---------------- edge scatter: agg[dst] += dinv[s]*dinv[d] * t[src] ----------------
template<int C>
__global__ void edge_kernel(const float* __restrict__ t, float* __restrict__ agg,
                            const int* __restrict__ src, const int* __restrict__ dst,
                            const float* __restrict__ dinv, int E) {
    const int TPE = C / 4;
    int gid = blockIdx.x * blockDim.x + threadIdx.x;
    int e = gid / TPE;
    int j = gid % TPE;
    if (e >= E) return;
    int s = src[e];
    int d = dst[e];
    float nrm = dinv[s] * dinv[d];
    float4 v = *(const float4*)(t + (size_t)s * C + j * 4);
    v.x *= nrm; v.y *= nrm; v.z *= nrm; v.w *= nrm;
    red_add_v4(agg + (size_t)d * C + j * 4, v);
}

// ---------------- GEMM: out[i] = act(in[i] @ W (+ b)) ----------------
// ACT: 0=none, 1=tanh, 2=relu
template<int IN, int OUT, int ACT, bool HASB>
__global__ void gemm_kernel(const float* __restrict__ in, const float* __restrict__ W,
                            const float* __restrict__ b, float* __restrict__ out, int N) {
    __shared__ __align__(16) float Ws[IN * OUT];
    __shared__ __align__(16) float bs[OUT];
    for (int i = threadIdx.x; i < IN * OUT; i += blockDim.x) Ws[i] = W[i];
    if (HASB) for (int i = threadIdx.x; i < OUT; i += blockDim.x) bs[i] = b[i];
    __syncthreads();

    int node = blockIdx.x * blockDim.x + threadIdx.x;
    if (node >= N) return;
    const float* row = in + (size_t)node * IN;

    unsigned long long acc[OUT / 2];
    #pragma unroll
    for (int j = 0; j < OUT / 2; j++) {
        if (HASB) {
            float2 bb = *(const float2*)&bs[2 * j];
            unsigned long long p;
            asm("mov.b64 %0, {%1, %2};" : "=l"(p)
                : "r"(__float_as_uint(bb.x)), "r"(__float_as_uint(bb.y)));
            acc[j] = p;
        } else {
            acc[j] = 0ULL;
        }
    }

    #pragma unroll 4
    for (int k = 0; k < IN; k++) {
        unsigned long long xk2 = pack2(row[k]);
        const unsigned long long* wrow = (const unsigned long long*)&Ws[k * OUT];
        #pragma unroll
        for (int j = 0; j < OUT / 2; j++)
            acc[j] = fma2(xk2, wrow[j], acc[j]);
    }

    float* o = out + (size_t)node * OUT;
    #pragma unroll
    for (int j = 0; j < OUT / 2; j++) {
        float2 v;
        unsigned int lo, hi;
        asm("mov.b64 {%0, %1}, %2;" : "=r"(lo), "=r"(hi) : "l"(acc[j]));
        v.x = __uint_as_float(lo); v.y = __uint_as_float(hi);
        if (ACT == 1) { v.x = tanhf(v.x); v.y = tanhf(v.y); }
        if (ACT == 2) { v.x = fmaxf(v.x, 0.f); v.y = fmaxf(v.y, 0.f); }
        *(float2*)(o + 2 * j) = v;
    }
}

// ---------------- pooling: per-graph max + sum + count over 32 channels ----------------
__global__ void pool_kernel(const float* __restrict__ h, const int* __restrict__ batch,
                            float* __restrict__ gmax, float* __restrict__ gsum,
                            float* __restrict__ gcnt, int N) {
    int gid = blockIdx.x * blockDim.x + threadIdx.x;
    int node = gid / 8;
    int j = gid % 8;
    if (node >= N) return;
    float4 v = *(const float4*)(h + (size_t)node * 32 + j * 4);
    int g = batch[node];
    int base = g * 32 + j * 4;
    // h is post-ReLU (>=0) so int compare == float compare; gmax init = 0
    atomicMax((int*)gmax + base + 0, __float_as_int(v.x));
    atomicMax((int*)gmax + base + 1, __float_as_int(v.y));
    atomicMax((int*)gmax + base + 2, __float_as_int(v.z));
    atomicMax((int*)gmax + base + 3, __float_as_int(v.w));
    red_add_v4(gsum + base, v);
    if (j == 0) atomicAdd(&gcnt[g], 1.0f);
}

// ---------------- final linear: out[g][o] = [gmax|gmean] @ Wout + bout ----------------
__global__ void out_kernel(const float* __restrict__ gmax, const float* __restrict__ gsum,
                           const float* __restrict__ gcnt, const float* __restrict__ Wout,
                           const float* __restrict__ bout, float* __restrict__ out) {
    int gid = blockIdx.x * blockDim.x + threadIdx.x;
    if (gid >= N_GRAPHS_C * 10) return;
    int g = gid / 10, o = gid % 10;
    float inv = 1.0f / fmaxf(gcnt[g], 1.0f);
    float acc = bout[o];
    #pragma unroll
    for (int k = 0; k < 32; k++) acc += gmax[g * 32 + k] * Wout[k * 10 + o];
    #pragma unroll
    for (int k = 0; k < 32; k++) acc += gsum[g * 32 + k] * inv * Wout[(32 + k) * 10 + o];
    out[gid] = acc;
}

// ---------------- launch ----------------
static inline int cdiv(long long a, int b) { return (int)((a + b - 1) / b); }

extern "C" void kernel_launch(void* const* d_in, const int* in_sizes, int n_in,
                              void* d_out, int out_size) {
    const float* x     = (const float*)d_in[0];
    const int*   ei    = (const int*)d_in[1];    // int32! (JAX x64 disabled)
    const int*   batch = (const int*)d_in[2];    // int32!
    const float* W0 = (const float*)d_in[3];
    const float* b0 = (const float*)d_in[4];
    const float* W1 = (const float*)d_in[5];
    const float* b1 = (const float*)d_in[6];
    const float* W2 = (const float*)d_in[7];
    const float* b2 = (const float*)d_in[8];
    const float* W3 = (const float*)d_in[9];
    const float* b3 = (const float*)d_in[10];
    const float* Wout = (const float*)d_in[11];
    const float* bout = (const float*)d_in[12];

    int N = in_sizes[0] / 8;
    int E = in_sizes[1] / 2;
    const int* src = ei;
    const int* dst = ei + E;

    float *bufA, *bufB, *bufC, *dinv, *gmax, *gsum, *gcnt;
    int *deg;
    cudaGetSymbolAddress((void**)&bufA, g_bufA);
    cudaGetSymbolAddress((void**)&bufB, g_bufB);
    cudaGetSymbolAddress((void**)&bufC, g_bufC);
    cudaGetSymbolAddress((void**)&deg,  g_deg);
    cudaGetSymbolAddress((void**)&dinv, g_dinv);
    cudaGetSymbolAddress((void**)&gmax, g_gmax);
    cudaGetSymbolAddress((void**)&gsum, g_gsum);
    cudaGetSymbolAddress((void**)&gcnt, g_gcnt);

    const int B = 256;

    cudaMemsetAsync(deg,  0, (size_t)N * sizeof(int));
    cudaMemsetAsync(gmax, 0, (size_t)N_GRAPHS_C * 32 * sizeof(float));
    cudaMemsetAsync(gsum, 0, (size_t)N_GRAPHS_C * 32 * sizeof(float));
    cudaMemsetAsync(gcnt, 0, (size_t)N_GRAPHS_C * sizeof(float));

    deg_kernel<<<cdiv(E, B), B>>>(dst, deg, E);
    dinv_kernel<<<cdiv(N, B), B>>>(deg, dinv, N);

    // Layer 0: aggregate at C=8 first (AGG(X W) == (AGG X) W), then GEMM 8->64 + b0 + tanh
    prep_kernel<8, false, false, false><<<cdiv((long long)N * 2, B), B>>>(x, nullptr, bufA, dinv, nullptr, N);
    edge_kernel<8><<<cdiv((long long)E * 2, B), B>>>(x, bufA, src, dst, dinv, E);
    gemm_kernel<8, 64, 1, true><<<cdiv(N, B), B>>>(bufA, W0, b0, bufB, N);   // h1 = tanh(...) in bufB

    // Layer 1: aggregate at C=64, GEMM 64->64 + b1 + relu
    prep_kernel<64, false, false, false><<<cdiv((long long)N * 16, B), B>>>(bufB, nullptr, bufA, dinv, nullptr, N);
    edge_kernel<64><<<cdiv((long long)E * 16, B), B>>>(bufB, bufA, src, dst, dinv, E);
    gemm_kernel<64, 64, 2, true><<<cdiv(N, B), B>>>(bufA, W1, b1, bufB, N);  // h2 = relu(...) in bufB

    // Layer 2: GEMM 64->32 first (no bias), aggregate at C=32 with +b2; relu deferred
    gemm_kernel<64, 32, 0, false><<<cdiv(N, B), B>>>(bufB, W2, nullptr, bufA, N);  // t2 in bufA
    prep_kernel<32, false, true, false><<<cdiv((long long)N * 8, B), B>>>(bufA, nullptr, bufB, dinv, b2, N);
    edge_kernel<32><<<cdiv((long long)E * 8, B), B>>>(bufA, bufB, src, dst, dinv, E);  // agg2 in bufB

    // Layer 3: relu(agg2) -> h3, aggregate at C=32, GEMM 32->32 + b3 + relu
    prep_kernel<32, true, false, true><<<cdiv((long long)N * 8, B), B>>>(bufB, bufA, bufC, dinv, nullptr, N);
    edge_kernel<32><<<cdiv((long long)E * 8, B), B>>>(bufA, bufC, src, dst, dinv, E);  // agg3 in bufC
    gemm_kernel<32, 32, 2, true><<<cdiv(N, B), B>>>(bufC, W3, b3, bufB, N);  // h4 = relu(...) in bufB

    // Pooling + output head
    pool_kernel<<<cdiv((long long)N * 8, B), B>>>(bufB, batch, gmax, gsum, gcnt, N);
    out_kernel<<<cdiv(N_GRAPHS_C * 10, B), B>>>(gmax, gsum, gcnt, Wout, bout, (float*)d_out);
}